// round 2
// baseline (speedup 1.0000x reference)
#include <cuda_runtime.h>

#define BB 8
#define NN 2048
#define DD 128
#define NEG_INF_F (-9.0e15f)
#define ALPHA_F 0.2f

// Scratch (no cudaMalloc allowed)
__device__ float g_Wh[BB * NN * DD];   // 8 MB
__device__ float g_es[BB * NN];
__device__ float g_ed[BB * NN];

// ---------------------------------------------------------------------------
// Kernel 1: Wh = h @ W  ;  e_src = Wh . a_src ;  e_dst = Wh . a_dst
// Grid: 256 blocks x 256 threads, 64 rows per block.
// ---------------------------------------------------------------------------
__global__ __launch_bounds__(256) void k_proj(const float* __restrict__ h,
                                              const float* __restrict__ W,
                                              const float* __restrict__ a_src,
                                              const float* __restrict__ a_dst) {
    __shared__ float hs[64][128];

    const int t  = threadIdx.x;
    const int tx = t & 31;   // d-group: d = tx*4 .. tx*4+3
    const int ty = t >> 5;   // i-group: rows ty*8 .. ty*8+7
    const int row0 = blockIdx.x * 64;

    // Load 64 rows of h into shared (2048 float4)
    const float4* h4  = ((const float4*)h) + (size_t)row0 * 32;
    float4*       hs4 = (float4*)hs;
#pragma unroll
    for (int q = 0; q < 8; q++) hs4[t + 256 * q] = h4[t + 256 * q];
    __syncthreads();

    float4 acc[8];
#pragma unroll
    for (int ii = 0; ii < 8; ii++) acc[ii] = make_float4(0.f, 0.f, 0.f, 0.f);

    const float4* W4 = (const float4*)W;
    for (int k = 0; k < 128; k++) {
        float4 w = __ldg(&W4[k * 32 + tx]);
#pragma unroll
        for (int ii = 0; ii < 8; ii++) {
            float hv = hs[ty * 8 + ii][k];
            acc[ii].x += hv * w.x;
            acc[ii].y += hv * w.y;
            acc[ii].z += hv * w.z;
            acc[ii].w += hv * w.w;
        }
    }

    float4 as = __ldg(((const float4*)a_src) + tx);
    float4 ad = __ldg(((const float4*)a_dst) + tx);
    float4* Wh4 = (float4*)g_Wh;
#pragma unroll
    for (int ii = 0; ii < 8; ii++) {
        int row = row0 + ty * 8 + ii;
        Wh4[(size_t)row * 32 + tx] = acc[ii];
        float psrc = acc[ii].x * as.x + acc[ii].y * as.y + acc[ii].z * as.z + acc[ii].w * as.w;
        float pdst = acc[ii].x * ad.x + acc[ii].y * ad.y + acc[ii].z * ad.z + acc[ii].w * ad.w;
#pragma unroll
        for (int o = 16; o > 0; o >>= 1) {
            psrc += __shfl_xor_sync(0xffffffffu, psrc, o);
            pdst += __shfl_xor_sync(0xffffffffu, pdst, o);
        }
        if (tx == 0) {
            g_es[row] = psrc;
            g_ed[row] = pdst;
        }
    }
}

// ---------------------------------------------------------------------------
// Kernel 2: fused masked additive attention + online softmax + P @ Wh
// Block: (i-tile of 64 rows) x (batch). 256 threads.
//   GEMM layout:    tx = t&31 -> d = tx*4..+3 ; ty = t>>5 -> i = ty*8..+7
//   softmax layout: row = t>>2 (64 rows), sub = t&3 -> jj = sub*8..+8 (TJ=32)
// ---------------------------------------------------------------------------
__global__ __launch_bounds__(256) void k_attn(const int* __restrict__ adj,
                                              float* __restrict__ out) {
    __shared__ float Whs[32][128];     // 16 KB  (j-tile of Wh)
    __shared__ float ps[64][32];       //  8 KB  (probabilities)
    __shared__ float es_s[64];
    __shared__ float sm_m[64];
    __shared__ float sm_l[64];
    __shared__ float sm_scale[64];

    const int t   = threadIdx.x;
    const int tx  = t & 31;
    const int ty  = t >> 5;
    const int row = t >> 2;
    const int sub = t & 3;
    const int b   = blockIdx.y;
    const int i0  = blockIdx.x * 64;

    if (t < 64) {
        es_s[t] = g_es[b * NN + i0 + t];
        sm_m[t] = NEG_INF_F;
        sm_l[t] = 0.f;
    }

    float4 acc[8];
#pragma unroll
    for (int ii = 0; ii < 8; ii++) acc[ii] = make_float4(0.f, 0.f, 0.f, 0.f);

    const float4* Wh4 = ((const float4*)g_Wh) + (size_t)b * NN * 32;
    const float*  ed  = g_ed + b * NN;

    for (int j0 = 0; j0 < NN; j0 += 32) {
        __syncthreads();  // previous tile's GEMM done reading Whs/ps/sm_scale

        // --- stage A: load Wh j-tile into shared (1024 float4) ---
        float4* Whs4 = (float4*)Whs;
#pragma unroll
        for (int q = 0; q < 4; q++)
            Whs4[t + 256 * q] = Wh4[(size_t)j0 * 32 + t + 256 * q];

        // --- stage B: logits + online softmax (8 contiguous jj per thread) ---
        float s[8];
        float esr = es_s[row];
        const int* adjr = adj + (size_t)(i0 + row) * NN + j0 + sub * 8;
        const float* edr = ed + j0 + sub * 8;
        float tmax = NEG_INF_F;
#pragma unroll
        for (int q = 0; q < 8; q++) {
            float e = esr + __ldg(&edr[q]);
            e = e > 0.f ? e : ALPHA_F * e;           // leaky relu
            e = (__ldg(&adjr[q]) > 0) ? e : NEG_INF_F;
            s[q] = e;
            tmax = fmaxf(tmax, e);
        }
        // quad reduce (4 threads per row)
        tmax = fmaxf(tmax, __shfl_xor_sync(0xffffffffu, tmax, 1));
        tmax = fmaxf(tmax, __shfl_xor_sync(0xffffffffu, tmax, 2));

        float mold  = sm_m[row];
        float mnew  = fmaxf(mold, tmax);
        float scale = __expf(mold - mnew);
        float lsum  = 0.f;
#pragma unroll
        for (int q = 0; q < 8; q++) {
            float p = __expf(s[q] - mnew);
            ps[row][sub * 8 + q] = p;
            lsum += p;
        }
        lsum += __shfl_xor_sync(0xffffffffu, lsum, 1);
        lsum += __shfl_xor_sync(0xffffffffu, lsum, 2);
        if (sub == 0) {
            sm_m[row]     = mnew;
            sm_scale[row] = scale;
            sm_l[row]     = sm_l[row] * scale + lsum;
        }
        __syncthreads();

        // --- stage C: rescale accumulators, then P @ Wh (register tiled) ---
#pragma unroll
        for (int ii = 0; ii < 8; ii++) {
            float sc = sm_scale[ty * 8 + ii];
            acc[ii].x *= sc; acc[ii].y *= sc; acc[ii].z *= sc; acc[ii].w *= sc;
        }
        const float4* ps4 = (const float4*)ps;  // [64][8]
#pragma unroll
        for (int j4 = 0; j4 < 8; j4++) {
            float4 w0 = ((const float4*)Whs[j4 * 4 + 0])[tx];
            float4 w1 = ((const float4*)Whs[j4 * 4 + 1])[tx];
            float4 w2 = ((const float4*)Whs[j4 * 4 + 2])[tx];
            float4 w3 = ((const float4*)Whs[j4 * 4 + 3])[tx];
#pragma unroll
            for (int ii = 0; ii < 8; ii++) {
                float4 p = ps4[(ty * 8 + ii) * 8 + j4];  // warp broadcast
                acc[ii].x += p.x * w0.x + p.y * w1.x + p.z * w2.x + p.w * w3.x;
                acc[ii].y += p.x * w0.y + p.y * w1.y + p.z * w2.y + p.w * w3.y;
                acc[ii].z += p.x * w0.z + p.y * w1.z + p.z * w2.z + p.w * w3.z;
                acc[ii].w += p.x * w0.w + p.y * w1.w + p.z * w2.w + p.w * w3.w;
            }
        }
    }

    __syncthreads();
    // --- epilogue: divide by softmax denominator, write out ---
#pragma unroll
    for (int ii = 0; ii < 8; ii++) {
        int i = ty * 8 + ii;
        float inv = 1.0f / sm_l[i];
        float4 r = acc[ii];
        r.x *= inv; r.y *= inv; r.z *= inv; r.w *= inv;
        ((float4*)out)[((size_t)b * NN + i0 + i) * 32 + tx] = r;
    }
}

// ---------------------------------------------------------------------------
extern "C" void kernel_launch(void* const* d_in, const int* in_sizes, int n_in,
                              void* d_out, int out_size) {
    const float* h     = (const float*)d_in[0];
    const int*   adj   = (const int*)d_in[1];
    const float* W     = (const float*)d_in[2];
    const float* a_src = (const float*)d_in[3];
    const float* a_dst = (const float*)d_in[4];
    float* out = (float*)d_out;

    k_proj<<<256, 256>>>(h, W, a_src, a_dst);
    k_attn<<<dim3(NN / 64, BB), 256>>>(adj, out);
}

// round 4
// speedup vs baseline: 1.8157x; 1.8157x over previous
#include <cuda_runtime.h>
#include <cstdint>

#define BB 8
#define NN 2048
#define DD 128
#define ALPHA_F 0.2f
#define LOG2E_F 1.4426950408889634f

// ---------------- device scratch (no cudaMalloc allowed) ----------------
__device__ float    g_Wh[BB * NN * DD];       // 8 MB, [b*N + j][d], tf32-rounded
__device__ float    g_es[BB * NN];
__device__ float    g_ed[BB * NN];
__device__ float    g_edmax[BB];
__device__ unsigned g_mask[NN * (NN / 32)];   // 512 KB packed adjacency bits

// ---------------- helpers ----------------
__device__ __forceinline__ uint32_t smem_u32(const void* p) {
    uint32_t a;
    asm("{ .reg .u64 t; cvta.to.shared.u64 t, %1; cvt.u32.u64 %0, t; }" : "=r"(a) : "l"(p));
    return a;
}
__device__ __forceinline__ unsigned long long pk2(float a, float b) {
    unsigned long long r; asm("mov.b64 %0, {%1,%2};" : "=l"(r) : "f"(a), "f"(b)); return r;
}
__device__ __forceinline__ void upk2(unsigned long long v, float& a, float& b) {
    asm("mov.b64 {%0,%1}, %2;" : "=f"(a), "=f"(b) : "l"(v));
}
__device__ __forceinline__ void ffma2(unsigned long long& d, unsigned long long a, unsigned long long b) {
    asm("fma.rn.f32x2 %0, %1, %2, %0;" : "+l"(d) : "l"(a), "l"(b));
}
__device__ __forceinline__ float ex2f(float x) {
    float r; asm("ex2.approx.ftz.f32 %0, %1;" : "=f"(r) : "f"(x)); return r;
}
__device__ __forceinline__ float tf32r(float x) {
    uint32_t u; asm("cvt.rna.tf32.f32 %0, %1;" : "=r"(u) : "f"(x)); return __uint_as_float(u);
}
__device__ __forceinline__ void cpasync16(uint32_t dst, const void* src) {
    asm volatile("cp.async.ca.shared.global [%0], [%1], 16;" :: "r"(dst), "l"(src));
}
#define CP_COMMIT() asm volatile("cp.async.commit_group;" ::: "memory")
#define CP_WAIT0()  asm volatile("cp.async.wait_group 0;" ::: "memory")

// tf32 m16n8k8 register MMA (base ISA, works on plain sm_103 target)
__device__ __forceinline__ void mma8(float* d, const uint32_t* a, const uint32_t* b) {
    asm volatile(
        "mma.sync.aligned.m16n8k8.row.col.f32.tf32.tf32.f32 "
        "{%0,%1,%2,%3}, {%4,%5,%6,%7}, {%8,%9}, {%0,%1,%2,%3};"
        : "+f"(d[0]), "+f"(d[1]), "+f"(d[2]), "+f"(d[3])
        : "r"(a[0]), "r"(a[1]), "r"(a[2]), "r"(a[3]), "r"(b[0]), "r"(b[1]));
}

// ===========================================================================
// Kernel 1: Wh = h@W (FFMA2), emit tf32-rounded Wh[row][d] + fp32 e_src/e_dst
// 256 blocks x 256 threads, 64 global rows per block.
// ===========================================================================
__global__ __launch_bounds__(256) void k_proj(const float* __restrict__ h,
                                              const float* __restrict__ W,
                                              const float* __restrict__ a_src,
                                              const float* __restrict__ a_dst) {
    __shared__ float sbuf[128 * 66];  // [k][row], pitch 66

    const int t = threadIdx.x, tx = t & 31, ty = t >> 5;
    const int grow0 = blockIdx.x * 64;  // global row (b*N + n)

    const float4* h4 = ((const float4*)h) + (size_t)grow0 * 32;
#pragma unroll
    for (int q = 0; q < 8; q++) {
        int idx = t + 256 * q;
        int row = idx >> 5, k4 = idx & 31;
        float4 v = h4[idx];
        sbuf[(k4 * 4 + 0) * 66 + row] = v.x;
        sbuf[(k4 * 4 + 1) * 66 + row] = v.y;
        sbuf[(k4 * 4 + 2) * 66 + row] = v.z;
        sbuf[(k4 * 4 + 3) * 66 + row] = v.w;
    }
    __syncthreads();

    unsigned long long ax[4] = {0, 0, 0, 0}, ay[4] = {0, 0, 0, 0},
                       az[4] = {0, 0, 0, 0}, aw[4] = {0, 0, 0, 0};
    const float4* W4 = (const float4*)W;
    for (int k = 0; k < 128; k++) {
        float4 w = __ldg(&W4[k * 32 + tx]);
        unsigned long long wxx = pk2(w.x, w.x), wyy = pk2(w.y, w.y);
        unsigned long long wzz = pk2(w.z, w.z), www = pk2(w.w, w.w);
        const float* hp = &sbuf[k * 66 + ty * 8];
#pragma unroll
        for (int pr = 0; pr < 4; pr++) {
            unsigned long long hh = *(const unsigned long long*)(hp + pr * 2);
            ffma2(ax[pr], hh, wxx);
            ffma2(ay[pr], hh, wyy);
            ffma2(az[pr], hh, wzz);
            ffma2(aw[pr], hh, www);
        }
    }

    float4 as = __ldg(((const float4*)a_src) + tx);
    float4 ad = __ldg(((const float4*)a_dst) + tx);
    float4* Wh4 = (float4*)g_Wh;
#pragma unroll
    for (int pr = 0; pr < 4; pr++) {
        float x0, x1, y0, y1, z0, z1, w0, w1;
        upk2(ax[pr], x0, x1); upk2(ay[pr], y0, y1);
        upk2(az[pr], z0, z1); upk2(aw[pr], w0, w1);
        int r0 = grow0 + ty * 8 + pr * 2;
        float4 v0 = make_float4(tf32r(x0), tf32r(y0), tf32r(z0), tf32r(w0));
        float4 v1 = make_float4(tf32r(x1), tf32r(y1), tf32r(z1), tf32r(w1));
        Wh4[(size_t)r0 * 32 + tx] = v0;
        Wh4[(size_t)(r0 + 1) * 32 + tx] = v1;
        float ps0 = x0 * as.x + y0 * as.y + z0 * as.z + w0 * as.w;
        float ps1 = x1 * as.x + y1 * as.y + z1 * as.z + w1 * as.w;
        float pd0 = x0 * ad.x + y0 * ad.y + z0 * ad.z + w0 * ad.w;
        float pd1 = x1 * ad.x + y1 * ad.y + z1 * ad.z + w1 * ad.w;
#pragma unroll
        for (int o = 16; o > 0; o >>= 1) {
            ps0 += __shfl_xor_sync(0xffffffffu, ps0, o);
            ps1 += __shfl_xor_sync(0xffffffffu, ps1, o);
            pd0 += __shfl_xor_sync(0xffffffffu, pd0, o);
            pd1 += __shfl_xor_sync(0xffffffffu, pd1, o);
        }
        if (tx == 0) {
            g_es[r0] = ps0; g_es[r0 + 1] = ps1;
            g_ed[r0] = pd0; g_ed[r0 + 1] = pd1;
        }
    }
}

// ===========================================================================
// Kernel 1b: pack adjacency into bitmask. 512 blocks x 256 threads.
// ===========================================================================
__global__ __launch_bounds__(256) void k_mask(const int* __restrict__ adj) {
    const int g = blockIdx.x * 256 + threadIdx.x;  // word index
    const int i = g >> 6, w = g & 63;
    const int4* a4 = ((const int4*)adj) + (size_t)i * 512 + w * 8;
    unsigned bits = 0;
#pragma unroll
    for (int q = 0; q < 8; q++) {
        int4 v = __ldg(&a4[q]);
        bits |= (v.x > 0 ? 1u : 0u) << (q * 4 + 0);
        bits |= (v.y > 0 ? 1u : 0u) << (q * 4 + 1);
        bits |= (v.z > 0 ? 1u : 0u) << (q * 4 + 2);
        bits |= (v.w > 0 ? 1u : 0u) << (q * 4 + 3);
    }
    g_mask[g] = bits;
}

// ===========================================================================
// Kernel 1c: per-batch max of e_dst
// ===========================================================================
__global__ __launch_bounds__(256) void k_edmax() {
    __shared__ float red[256];
    const int b = blockIdx.x, t = threadIdx.x;
    float m = -1e30f;
#pragma unroll
    for (int q = 0; q < 8; q++) m = fmaxf(m, g_ed[b * NN + t + 256 * q]);
    red[t] = m;
    __syncthreads();
    for (int s = 128; s > 0; s >>= 1) {
        if (t < s) red[t] = fmaxf(red[t], red[t + s]);
        __syncthreads();
    }
    if (t == 0) g_edmax[b] = red[0];
}

// ===========================================================================
// Kernel 2: fused masked attention + exp + tf32 mma.sync P@Wh
// grid (16, 8): 128 i-rows per block, 256 threads (8 warps, 4M x 2N).
// smem layout (dynamic, 62 KB):
//   Whs[2][32][136]f @ 0        (2 x 17408 B)   Wh j-tile, cp.async double buf
//   Ps[128][36]f     @ 34816    (18432 B)       probabilities (tf32)
//   eds[2048]f       @ 53248    (8192 B)
//   linv[128]f       @ 61440    (512 B)
// ===========================================================================
#define WHS_OFF  0u
#define WHS_BUFB 17408u
#define WHS_PIT  544u      // 136 floats
#define PS_OFF   34816u
#define PS_PIT   144u      // 36 floats
#define EDS_OFF  53248u
#define LINV_OFF 61440u
#define SMEM_SZ  61952u

__global__ __launch_bounds__(256) void k_attn(float* __restrict__ out) {
    extern __shared__ __align__(16) char smem[];
    const uint32_t sbase = smem_u32(smem);

    const int t = threadIdx.x, wid = t >> 5, lane = t & 31;
    const int gid = lane >> 2, tid4 = lane & 3;
    const int wm = wid & 3, wn = wid >> 2;          // 4 x 2 warp grid
    const int b = blockIdx.y, i0 = blockIdx.x * 128;
    const int row = t >> 1, half = t & 1;           // producer mapping

    // prefetch Wh tile 0 into buf 0
    const float4* Wh4b = ((const float4*)g_Wh) + (size_t)b * NN * 32;
    {
#pragma unroll
        for (int q = 0; q < 4; q++) {
            int idx = t + 256 * q;
            int r = idx >> 5, c4 = idx & 31;
            cpasync16(sbase + WHS_OFF + (uint32_t)(r * WHS_PIT + c4 * 16), &Wh4b[idx]);
        }
        CP_COMMIT();
    }

    // preload e_dst row
    {
        float4* ed4 = (float4*)(smem + EDS_OFF);
        const float4* edsrc = ((const float4*)g_ed) + b * 512;
        ed4[t] = edsrc[t];
        ed4[t + 256] = edsrc[t + 256];
    }
    __syncthreads();

    const float esr = __ldg(g_es + b * NN + i0 + row);
    const float edm = g_edmax[b];
    const float xm = esr + edm;
    const float m2r = fmaxf(xm, ALPHA_F * xm) * LOG2E_F;  // upper bound of row logits * log2e
    float lsum = 0.f;

    const unsigned short* mrow = ((const unsigned short*)g_mask) + (size_t)(i0 + row) * 128;
    float* psrow = (float*)(smem + PS_OFF + (uint32_t)row * PS_PIT);

    float acc[2][8][4];
#pragma unroll
    for (int mt = 0; mt < 2; mt++)
#pragma unroll
        for (int nt = 0; nt < 8; nt++)
#pragma unroll
            for (int c = 0; c < 4; c++) acc[mt][nt][c] = 0.f;

    for (int k = 0; k < 64; k++) {
        const int buf = k & 1;
        const int j0 = k * 32;
        CP_WAIT0();  // Wh tile k landed in Whs[buf]

        // ---- produce P tile: 16 j per thread ----
        {
            unsigned mb = (unsigned)__ldg(&mrow[k * 2 + half]);
            const float* edt = (const float*)(smem + EDS_OFF) + j0 + half * 16;
#pragma unroll
            for (int q = 0; q < 4; q++) {
                float4 ev = *(const float4*)(edt + q * 4);
                float4 pv;
                {
                    float x = esr + ev.x, lx = fmaxf(x, ALPHA_F * x);
                    float p = ex2f(fmaf(lx, LOG2E_F, -m2r));
                    p = (mb >> (q * 4 + 0)) & 1 ? p : 0.f; p = tf32r(p); lsum += p; pv.x = p;
                }
                {
                    float x = esr + ev.y, lx = fmaxf(x, ALPHA_F * x);
                    float p = ex2f(fmaf(lx, LOG2E_F, -m2r));
                    p = (mb >> (q * 4 + 1)) & 1 ? p : 0.f; p = tf32r(p); lsum += p; pv.y = p;
                }
                {
                    float x = esr + ev.z, lx = fmaxf(x, ALPHA_F * x);
                    float p = ex2f(fmaf(lx, LOG2E_F, -m2r));
                    p = (mb >> (q * 4 + 2)) & 1 ? p : 0.f; p = tf32r(p); lsum += p; pv.z = p;
                }
                {
                    float x = esr + ev.w, lx = fmaxf(x, ALPHA_F * x);
                    float p = ex2f(fmaf(lx, LOG2E_F, -m2r));
                    p = (mb >> (q * 4 + 3)) & 1 ? p : 0.f; p = tf32r(p); lsum += p; pv.w = p;
                }
                *(float4*)(psrow + half * 16 + q * 4) = pv;
            }
        }
        __syncthreads();  // P + Whs[buf] visible to all

        // ---- prefetch Wh tile k+1 into other buffer ----
        if (k < 63) {
            const float4* src = Wh4b + (size_t)(j0 + 32) * 32;
            uint32_t dst = sbase + WHS_OFF + (buf ^ 1) * WHS_BUFB;
#pragma unroll
            for (int q = 0; q < 4; q++) {
                int idx = t + 256 * q;
                int r = idx >> 5, c4 = idx & 31;
                cpasync16(dst + (uint32_t)(r * WHS_PIT + c4 * 16), &src[idx]);
            }
            CP_COMMIT();
        }

        // ---- consume: 64 HMMA per warp ----
        {
            const char* whsb = smem + WHS_OFF + buf * WHS_BUFB;
            const char* psb  = smem + PS_OFF;
            const int r0 = wm * 32 + gid;
#pragma unroll
            for (int kb = 0; kb < 4; kb++) {
                const int kk = kb * 8 + tid4;
                uint32_t a[8], bf[16];
                const char* pk  = psb + (uint32_t)kk * 4;
                a[0] = *(const uint32_t*)(pk + (r0)      * PS_PIT);
                a[1] = *(const uint32_t*)(pk + (r0 + 8)  * PS_PIT);
                a[2] = *(const uint32_t*)(pk + (r0)      * PS_PIT + 16);
                a[3] = *(const uint32_t*)(pk + (r0 + 8)  * PS_PIT + 16);
                a[4] = *(const uint32_t*)(pk + (r0 + 16) * PS_PIT);
                a[5] = *(const uint32_t*)(pk + (r0 + 24) * PS_PIT);
                a[6] = *(const uint32_t*)(pk + (r0 + 16) * PS_PIT + 16);
                a[7] = *(const uint32_t*)(pk + (r0 + 24) * PS_PIT + 16);
                const char* w0 = whsb + (uint32_t)kk * WHS_PIT + (wn * 64 + gid) * 4;
                const char* w1 = w0 + 4 * WHS_PIT;
#pragma unroll
                for (int nt = 0; nt < 8; nt++) {
                    bf[nt * 2]     = *(const uint32_t*)(w0 + nt * 32);
                    bf[nt * 2 + 1] = *(const uint32_t*)(w1 + nt * 32);
                }
#pragma unroll
                for (int mt = 0; mt < 2; mt++)
#pragma unroll
                    for (int nt = 0; nt < 8; nt++)
                        mma8(acc[mt][nt], &a[mt * 4], &bf[nt * 2]);
            }
        }
        __syncthreads();  // consume done -> P/Whs[buf] reusable
    }

    // ---- softmax denominators ----
    {
        float ltot = lsum + __shfl_xor_sync(0xffffffffu, lsum, 1);
        if (half == 0) *(float*)(smem + LINV_OFF + row * 4) = 1.0f / ltot;
    }
    __syncthreads();

    // ---- epilogue: normalize + write ----
    const float* linv = (const float*)(smem + LINV_OFF);
    float2* out2 = (float2*)out;
#pragma unroll
    for (int mt = 0; mt < 2; mt++) {
        int rA = wm * 32 + mt * 16 + gid;
        int rB = rA + 8;
        float ivA = linv[rA], ivB = linv[rB];
        size_t baseA = ((size_t)(b * NN + i0 + rA) * 128) >> 1;
        size_t baseB = ((size_t)(b * NN + i0 + rB) * 128) >> 1;
#pragma unroll
        for (int nt = 0; nt < 8; nt++) {
            int colh = (wn * 64 + nt * 8 + tid4 * 2) >> 1;
            out2[baseA + colh] = make_float2(acc[mt][nt][0] * ivA, acc[mt][nt][1] * ivA);
            out2[baseB + colh] = make_float2(acc[mt][nt][2] * ivB, acc[mt][nt][3] * ivB);
        }
    }
}

// ===========================================================================
extern "C" void kernel_launch(void* const* d_in, const int* in_sizes, int n_in,
                              void* d_out, int out_size) {
    const float* h     = (const float*)d_in[0];
    const int*   adj   = (const int*)d_in[1];
    const float* W     = (const float*)d_in[2];
    const float* a_src = (const float*)d_in[3];
    const float* a_dst = (const float*)d_in[4];
    float* out = (float*)d_out;

    cudaFuncSetAttribute(k_attn, cudaFuncAttributeMaxDynamicSharedMemorySize, SMEM_SZ);

    k_proj<<<256, 256>>>(h, W, a_src, a_dst);
    k_mask<<<512, 256>>>(adj);
    k_edmax<<<8, 256>>>();
    k_attn<<<dim3(16, 8), 256, SMEM_SZ>>>(out);
}

// round 5
// speedup vs baseline: 2.2470x; 1.2375x over previous
#include <cuda_runtime.h>
#include <cuda_fp16.h>
#include <cstdint>

#define BB 8
#define NN 2048
#define DD 128
#define ALPHA_F 0.2f
#define LOG2E_F 1.4426950408889634f

// ---------------- device scratch (no cudaMalloc allowed) ----------------
__device__ __half   g_Whh[BB * NN * DD];      // 4 MB, [b*N + j][d] fp16
__device__ float    g_es[BB * NN];
__device__ float    g_ed[BB * NN];
__device__ float    g_edmax[BB];
__device__ unsigned g_mask[NN * (NN / 32)];   // 512 KB packed adjacency bits

// ---------------- helpers ----------------
__device__ __forceinline__ uint32_t smem_u32(const void* p) {
    uint32_t a;
    asm("{ .reg .u64 t; cvta.to.shared.u64 t, %1; cvt.u32.u64 %0, t; }" : "=r"(a) : "l"(p));
    return a;
}
__device__ __forceinline__ unsigned long long pk2(float a, float b) {
    unsigned long long r; asm("mov.b64 %0, {%1,%2};" : "=l"(r) : "f"(a), "f"(b)); return r;
}
__device__ __forceinline__ void upk2(unsigned long long v, float& a, float& b) {
    asm("mov.b64 {%0,%1}, %2;" : "=f"(a), "=f"(b) : "l"(v));
}
__device__ __forceinline__ void ffma2(unsigned long long& d, unsigned long long a, unsigned long long b) {
    asm("fma.rn.f32x2 %0, %1, %2, %0;" : "+l"(d) : "l"(a), "l"(b));
}
__device__ __forceinline__ float ex2f(float x) {
    float r; asm("ex2.approx.ftz.f32 %0, %1;" : "=f"(r) : "f"(x)); return r;
}
__device__ __forceinline__ void cpasync16(uint32_t dst, const void* src) {
    asm volatile("cp.async.ca.shared.global [%0], [%1], 16;" :: "r"(dst), "l"(src));
}
#define CP_COMMIT() asm volatile("cp.async.commit_group;" ::: "memory")
#define CP_WAIT1()  asm volatile("cp.async.wait_group 1;" ::: "memory")

__device__ __forceinline__ void ldm4(uint32_t* r, uint32_t a) {
    asm volatile("ldmatrix.sync.aligned.m8n8.x4.shared.b16 {%0,%1,%2,%3}, [%4];"
                 : "=r"(r[0]), "=r"(r[1]), "=r"(r[2]), "=r"(r[3]) : "r"(a));
}
__device__ __forceinline__ void ldm4t(uint32_t* r, uint32_t a) {
    asm volatile("ldmatrix.sync.aligned.m8n8.x4.trans.shared.b16 {%0,%1,%2,%3}, [%4];"
                 : "=r"(r[0]), "=r"(r[1]), "=r"(r[2]), "=r"(r[3]) : "r"(a));
}
__device__ __forceinline__ void mma16(float* d, const uint32_t* a, const uint32_t* b) {
    asm volatile(
        "mma.sync.aligned.m16n8k16.row.col.f32.f16.f16.f32 "
        "{%0,%1,%2,%3}, {%4,%5,%6,%7}, {%8,%9}, {%0,%1,%2,%3};"
        : "+f"(d[0]), "+f"(d[1]), "+f"(d[2]), "+f"(d[3])
        : "r"(a[0]), "r"(a[1]), "r"(a[2]), "r"(a[3]), "r"(b[0]), "r"(b[1]));
}

// ===========================================================================
// Kernel 1: Wh = h@W (FFMA2), emit fp16 Wh[row][d] + fp32 e_src/e_dst
// 256 blocks x 256 threads, 64 global rows per block.
// ===========================================================================
__global__ __launch_bounds__(256) void k_proj(const float* __restrict__ h,
                                              const float* __restrict__ W,
                                              const float* __restrict__ a_src,
                                              const float* __restrict__ a_dst) {
    __shared__ float sbuf[128 * 66];  // [k][row], pitch 66

    const int t = threadIdx.x, tx = t & 31, ty = t >> 5;
    const int grow0 = blockIdx.x * 64;

    const float4* h4 = ((const float4*)h) + (size_t)grow0 * 32;
#pragma unroll
    for (int q = 0; q < 8; q++) {
        int idx = t + 256 * q;
        int row = idx >> 5, k4 = idx & 31;
        float4 v = h4[idx];
        sbuf[(k4 * 4 + 0) * 66 + row] = v.x;
        sbuf[(k4 * 4 + 1) * 66 + row] = v.y;
        sbuf[(k4 * 4 + 2) * 66 + row] = v.z;
        sbuf[(k4 * 4 + 3) * 66 + row] = v.w;
    }
    __syncthreads();

    unsigned long long ax[4] = {0, 0, 0, 0}, ay[4] = {0, 0, 0, 0},
                       az[4] = {0, 0, 0, 0}, aw[4] = {0, 0, 0, 0};
    const float4* W4 = (const float4*)W;
    for (int k = 0; k < 128; k++) {
        float4 w = __ldg(&W4[k * 32 + tx]);
        unsigned long long wxx = pk2(w.x, w.x), wyy = pk2(w.y, w.y);
        unsigned long long wzz = pk2(w.z, w.z), www = pk2(w.w, w.w);
        const float* hp = &sbuf[k * 66 + ty * 8];
#pragma unroll
        for (int pr = 0; pr < 4; pr++) {
            unsigned long long hh = *(const unsigned long long*)(hp + pr * 2);
            ffma2(ax[pr], hh, wxx);
            ffma2(ay[pr], hh, wyy);
            ffma2(az[pr], hh, wzz);
            ffma2(aw[pr], hh, www);
        }
    }

    float4 as = __ldg(((const float4*)a_src) + tx);
    float4 ad = __ldg(((const float4*)a_dst) + tx);
    uint2* Whh2 = (uint2*)g_Whh;
#pragma unroll
    for (int pr = 0; pr < 4; pr++) {
        float x0, x1, y0, y1, z0, z1, w0, w1;
        upk2(ax[pr], x0, x1); upk2(ay[pr], y0, y1);
        upk2(az[pr], z0, z1); upk2(aw[pr], w0, w1);
        int r0 = grow0 + ty * 8 + pr * 2;
        __half2 h01a = __floats2half2_rn(x0, y0), h23a = __floats2half2_rn(z0, w0);
        __half2 h01b = __floats2half2_rn(x1, y1), h23b = __floats2half2_rn(z1, w1);
        uint2 va, vb;
        va.x = *(uint32_t*)&h01a; va.y = *(uint32_t*)&h23a;
        vb.x = *(uint32_t*)&h01b; vb.y = *(uint32_t*)&h23b;
        Whh2[(size_t)r0 * 32 + tx] = va;
        Whh2[(size_t)(r0 + 1) * 32 + tx] = vb;
        float ps0 = x0 * as.x + y0 * as.y + z0 * as.z + w0 * as.w;
        float ps1 = x1 * as.x + y1 * as.y + z1 * as.z + w1 * as.w;
        float pd0 = x0 * ad.x + y0 * ad.y + z0 * ad.z + w0 * ad.w;
        float pd1 = x1 * ad.x + y1 * ad.y + z1 * ad.z + w1 * ad.w;
#pragma unroll
        for (int o = 16; o > 0; o >>= 1) {
            ps0 += __shfl_xor_sync(0xffffffffu, ps0, o);
            ps1 += __shfl_xor_sync(0xffffffffu, ps1, o);
            pd0 += __shfl_xor_sync(0xffffffffu, pd0, o);
            pd1 += __shfl_xor_sync(0xffffffffu, pd1, o);
        }
        if (tx == 0) {
            g_es[r0] = ps0; g_es[r0 + 1] = ps1;
            g_ed[r0] = pd0; g_ed[r0 + 1] = pd1;
        }
    }
}

// ===========================================================================
// Kernel 1b: pack adjacency into bitmask. 512 blocks x 256 threads.
// ===========================================================================
__global__ __launch_bounds__(256) void k_mask(const int* __restrict__ adj) {
    const int g = blockIdx.x * 256 + threadIdx.x;
    const int i = g >> 6, w = g & 63;
    const int4* a4 = ((const int4*)adj) + (size_t)i * 512 + w * 8;
    unsigned bits = 0;
#pragma unroll
    for (int q = 0; q < 8; q++) {
        int4 v = __ldg(&a4[q]);
        bits |= (v.x > 0 ? 1u : 0u) << (q * 4 + 0);
        bits |= (v.y > 0 ? 1u : 0u) << (q * 4 + 1);
        bits |= (v.z > 0 ? 1u : 0u) << (q * 4 + 2);
        bits |= (v.w > 0 ? 1u : 0u) << (q * 4 + 3);
    }
    g_mask[g] = bits;
}

// ===========================================================================
// Kernel 1c: per-batch max of e_dst
// ===========================================================================
__global__ __launch_bounds__(256) void k_edmax() {
    __shared__ float red[256];
    const int b = blockIdx.x, t = threadIdx.x;
    float m = -1e30f;
#pragma unroll
    for (int q = 0; q < 8; q++) m = fmaxf(m, g_ed[b * NN + t + 256 * q]);
    red[t] = m;
    __syncthreads();
    for (int s = 128; s > 0; s >>= 1) {
        if (t < s) red[t] = fmaxf(red[t], red[t + s]);
        __syncthreads();
    }
    if (t == 0) g_edmax[b] = red[0];
}

// ===========================================================================
// Kernel 2: fused masked attention + exp + fp16 mma.sync P@Wh
// grid (16, 8): 128 i-rows per block, 256 threads (8 warps, 4M x 2N).
// One __syncthreads per tile; cp.async 3-deep Wh ring; 2-deep P buffer.
// smem:
//   Whs[3][32 x 272B]  @ 0       (26112 B)  fp16 Wh tile, pitch 272
//   Ps [2][128 x 80B]  @ 26112   (20480 B)  fp16 probabilities, pitch 80
//   eds[2048]f         @ 46592   (8192 B)
//   linv[128]f         @ 54784   (512 B)
// ===========================================================================
#define WHS_OFF  0u
#define WHS_BUF  8704u
#define WHS_PIT  272u
#define PS_OFF   26112u
#define PS_BUF   10240u
#define PS_PIT   80u
#define EDS_OFF  46592u
#define LINV_OFF 54784u
#define SMEM_SZ  55296u

__global__ __launch_bounds__(256) void k_attn(float* __restrict__ out) {
    extern __shared__ __align__(16) char smem[];
    const uint32_t sbase = smem_u32(smem);

    const int t = threadIdx.x, wid = t >> 5, lane = t & 31;
    const int gid = lane >> 2, tid4 = lane & 3;
    const int wm = wid & 3, wn = wid >> 2;          // 4 x 2 warp grid
    const int b = blockIdx.y, i0 = blockIdx.x * 128;
    const int row = t >> 1, half = t & 1;           // producer mapping

    const __half* Whb = g_Whh + (size_t)b * NN * DD;

    // ldmatrix lane offsets (buffer-relative)
    const uint32_t offA = (uint32_t)((wm * 32 + (lane & 15)) * PS_PIT + (lane >> 4) * 16);
    const uint32_t offB = (uint32_t)((((lane >> 3) & 1) * 8 + (lane & 7)) * WHS_PIT +
                                     wn * 128 + (lane >> 4) * 16);

    // ---- prologue: cp Wh tile 0, tile 1; load eds ----
    {
        const int r = t >> 4, c = t & 15;
#pragma unroll
        for (int q = 0; q < 2; q++) {
            int idx = t + 256 * q;
            int rr = idx >> 4, cc = idx & 15;
            cpasync16(sbase + WHS_OFF + (uint32_t)(rr * WHS_PIT + cc * 16),
                      Whb + (size_t)rr * DD + cc * 8);
        }
        CP_COMMIT();
#pragma unroll
        for (int q = 0; q < 2; q++) {
            int idx = t + 256 * q;
            int rr = idx >> 4, cc = idx & 15;
            cpasync16(sbase + WHS_OFF + WHS_BUF + (uint32_t)(rr * WHS_PIT + cc * 16),
                      Whb + (size_t)(32 + rr) * DD + cc * 8);
        }
        CP_COMMIT();
        (void)r; (void)c;
    }
    {
        float4* ed4 = (float4*)(smem + EDS_OFF);
        const float4* edsrc = ((const float4*)g_ed) + b * 512;
        ed4[t] = edsrc[t];
        ed4[t + 256] = edsrc[t + 256];
    }
    __syncthreads();  // eds visible for producer

    const float esr = __ldg(g_es + b * NN + i0 + row);
    const float edm = __ldg(&g_edmax[b]);
    const float xm = esr + edm;
    const float m2r = fmaxf(xm, ALPHA_F * xm) * LOG2E_F;
    float lsum = 0.f;

    const unsigned short* mrow = ((const unsigned short*)g_mask) + (size_t)(i0 + row) * 128;

    float acc[2][8][4];
#pragma unroll
    for (int mt = 0; mt < 2; mt++)
#pragma unroll
        for (int nt = 0; nt < 8; nt++)
#pragma unroll
            for (int c = 0; c < 4; c++) acc[mt][nt][c] = 0.f;

    // produce P(0)
    {
        unsigned mb = (unsigned)__ldg(&mrow[half]);
        const float* edt = (const float*)(smem + EDS_OFF) + half * 16;
        uint32_t hreg[8];
#pragma unroll
        for (int q = 0; q < 4; q++) {
            float4 ev = *(const float4*)(edt + q * 4);
            float x0 = esr + ev.x, l0 = fmaxf(x0, ALPHA_F * x0);
            float p0 = ex2f(fmaf(l0, LOG2E_F, -m2r)); p0 = (mb >> (q * 4 + 0)) & 1 ? p0 : 0.f;
            float x1 = esr + ev.y, l1 = fmaxf(x1, ALPHA_F * x1);
            float p1 = ex2f(fmaf(l1, LOG2E_F, -m2r)); p1 = (mb >> (q * 4 + 1)) & 1 ? p1 : 0.f;
            float x2 = esr + ev.z, l2 = fmaxf(x2, ALPHA_F * x2);
            float p2 = ex2f(fmaf(l2, LOG2E_F, -m2r)); p2 = (mb >> (q * 4 + 2)) & 1 ? p2 : 0.f;
            float x3 = esr + ev.w, l3 = fmaxf(x3, ALPHA_F * x3);
            float p3 = ex2f(fmaf(l3, LOG2E_F, -m2r)); p3 = (mb >> (q * 4 + 3)) & 1 ? p3 : 0.f;
            lsum += (p0 + p1) + (p2 + p3);
            __half2 ha = __floats2half2_rn(p0, p1), hb = __floats2half2_rn(p2, p3);
            hreg[q * 2] = *(uint32_t*)&ha; hreg[q * 2 + 1] = *(uint32_t*)&hb;
        }
        uint4* dst = (uint4*)(smem + PS_OFF + (uint32_t)(row * PS_PIT + half * 32));
        dst[0] = make_uint4(hreg[0], hreg[1], hreg[2], hreg[3]);
        dst[1] = make_uint4(hreg[4], hreg[5], hreg[6], hreg[7]);
    }
    CP_WAIT1();      // Wh tile 0 landed
    __syncthreads(); // P(0) + Wh(0) visible

    int wbuf = 2;  // (k+2) % 3
    int rbuf = 0;  // k % 3
    for (int k = 0; k < 64; k++) {
        // ---- stage 1: cp.async Wh(k+2) ----
        if (k < 62) {
            const int j2 = (k + 2) * 32;
            uint32_t dstb = sbase + WHS_OFF + (uint32_t)wbuf * WHS_BUF;
#pragma unroll
            for (int q = 0; q < 2; q++) {
                int idx = t + 256 * q;
                int rr = idx >> 4, cc = idx & 15;
                cpasync16(dstb + (uint32_t)(rr * WHS_PIT + cc * 16),
                          Whb + (size_t)(j2 + rr) * DD + cc * 8);
            }
        }
        CP_COMMIT();

        // ---- stage 2: produce P(k+1) ----
        if (k < 63) {
            const int kt = k + 1;
            unsigned mb = (unsigned)__ldg(&mrow[kt * 2 + half]);
            const float* edt = (const float*)(smem + EDS_OFF) + kt * 32 + half * 16;
            uint32_t hreg[8];
#pragma unroll
            for (int q = 0; q < 4; q++) {
                float4 ev = *(const float4*)(edt + q * 4);
                float x0 = esr + ev.x, l0 = fmaxf(x0, ALPHA_F * x0);
                float p0 = ex2f(fmaf(l0, LOG2E_F, -m2r)); p0 = (mb >> (q * 4 + 0)) & 1 ? p0 : 0.f;
                float x1 = esr + ev.y, l1 = fmaxf(x1, ALPHA_F * x1);
                float p1 = ex2f(fmaf(l1, LOG2E_F, -m2r)); p1 = (mb >> (q * 4 + 1)) & 1 ? p1 : 0.f;
                float x2 = esr + ev.z, l2 = fmaxf(x2, ALPHA_F * x2);
                float p2 = ex2f(fmaf(l2, LOG2E_F, -m2r)); p2 = (mb >> (q * 4 + 2)) & 1 ? p2 : 0.f;
                float x3 = esr + ev.w, l3 = fmaxf(x3, ALPHA_F * x3);
                float p3 = ex2f(fmaf(l3, LOG2E_F, -m2r)); p3 = (mb >> (q * 4 + 3)) & 1 ? p3 : 0.f;
                lsum += (p0 + p1) + (p2 + p3);
                __half2 ha = __floats2half2_rn(p0, p1), hb = __floats2half2_rn(p2, p3);
                hreg[q * 2] = *(uint32_t*)&ha; hreg[q * 2 + 1] = *(uint32_t*)&hb;
            }
            uint4* dst = (uint4*)(smem + PS_OFF + (uint32_t)((kt & 1) * PS_BUF) +
                                  (uint32_t)(row * PS_PIT + half * 32));
            dst[0] = make_uint4(hreg[0], hreg[1], hreg[2], hreg[3]);
            dst[1] = make_uint4(hreg[4], hreg[5], hreg[6], hreg[7]);
        }

        // ---- stage 3: MMA(k) ----
        {
            const uint32_t psB = sbase + PS_OFF + (uint32_t)((k & 1) * PS_BUF);
            const uint32_t whB = sbase + WHS_OFF + (uint32_t)rbuf * WHS_BUF;
#pragma unroll
            for (int kb = 0; kb < 2; kb++) {
                uint32_t A0[4], A1[4], Bv[4][4];
                ldm4(A0, psB + offA + kb * 32);
                ldm4(A1, psB + offA + 16 * PS_PIT + kb * 32);
#pragma unroll
                for (int nb2 = 0; nb2 < 4; nb2++)
                    ldm4t(Bv[nb2], whB + offB + nb2 * 32 + kb * 16 * WHS_PIT);
#pragma unroll
                for (int nb2 = 0; nb2 < 4; nb2++) {
                    mma16(acc[0][nb2 * 2],     A0, &Bv[nb2][0]);
                    mma16(acc[0][nb2 * 2 + 1], A0, &Bv[nb2][2]);
                    mma16(acc[1][nb2 * 2],     A1, &Bv[nb2][0]);
                    mma16(acc[1][nb2 * 2 + 1], A1, &Bv[nb2][2]);
                }
            }
        }

        CP_WAIT1();       // Wh(k+1) complete (own thread)
        __syncthreads();  // all: P(k+1), Wh(k+1) visible; bufs reusable

        wbuf = wbuf == 2 ? 0 : wbuf + 1;
        rbuf = rbuf == 2 ? 0 : rbuf + 1;
    }

    // ---- softmax denominators ----
    {
        float ltot = lsum + __shfl_xor_sync(0xffffffffu, lsum, 1);
        if (half == 0) *(float*)(smem + LINV_OFF + row * 4) = 1.0f / ltot;
    }
    __syncthreads();

    // ---- epilogue: normalize + write ----
    const float* linv = (const float*)(smem + LINV_OFF);
    float2* out2 = (float2*)out;
#pragma unroll
    for (int mt = 0; mt < 2; mt++) {
        int rA = wm * 32 + mt * 16 + gid;
        int rB = rA + 8;
        float ivA = linv[rA], ivB = linv[rB];
        size_t baseA = ((size_t)(b * NN + i0 + rA) * 128) >> 1;
        size_t baseB = ((size_t)(b * NN + i0 + rB) * 128) >> 1;
#pragma unroll
        for (int nt = 0; nt < 8; nt++) {
            int colh = (wn * 64 + nt * 8 + tid4 * 2) >> 1;
            out2[baseA + colh] = make_float2(acc[mt][nt][0] * ivA, acc[mt][nt][1] * ivA);
            out2[baseB + colh] = make_float2(acc[mt][nt][2] * ivB, acc[mt][nt][3] * ivB);
        }
    }
}

// ===========================================================================
extern "C" void kernel_launch(void* const* d_in, const int* in_sizes, int n_in,
                              void* d_out, int out_size) {
    const float* h     = (const float*)d_in[0];
    const int*   adj   = (const int*)d_in[1];
    const float* W     = (const float*)d_in[2];
    const float* a_src = (const float*)d_in[3];
    const float* a_dst = (const float*)d_in[4];
    float* out = (float*)d_out;

    cudaFuncSetAttribute(k_attn, cudaFuncAttributeMaxDynamicSharedMemorySize, SMEM_SZ);

    k_proj<<<256, 256>>>(h, W, a_src, a_dst);
    k_mask<<<512, 256>>>(adj);
    k_edmax<<<8, 256>>>();
    k_attn<<<dim3(16, 8), 256, SMEM_SZ>>>(out);
}

// round 10
// speedup vs baseline: 4.0908x; 1.8205x over previous
#include <cuda_runtime.h>
#include <cuda_fp16.h>
#include <cstdint>

#define BB 8
#define NN 2048
#define DD 128
#define ALPHA_F 0.2f
#define LOG2E_F 1.4426950408889634f

// ---------------- device scratch (no cudaMalloc allowed) ----------------
__device__ __half   g_Whh[BB * NN * DD];      // 4 MB, [b*N + j][d] fp16
__device__ float    g_es[BB * NN];
__device__ float    g_ed[BB * NN];
__device__ float    g_edmax[BB];
__device__ unsigned g_mask[NN * (NN / 32)];   // 512 KB packed adjacency bits

// ---------------- helpers ----------------
__device__ __forceinline__ uint32_t smem_u32(const void* p) {
    uint32_t a;
    asm("{ .reg .u64 t; cvta.to.shared.u64 t, %1; cvt.u32.u64 %0, t; }" : "=r"(a) : "l"(p));
    return a;
}
__device__ __forceinline__ unsigned long long pk2(float a, float b) {
    unsigned long long r; asm("mov.b64 %0, {%1,%2};" : "=l"(r) : "f"(a), "f"(b)); return r;
}
__device__ __forceinline__ void upk2(unsigned long long v, float& a, float& b) {
    asm("mov.b64 {%0,%1}, %2;" : "=f"(a), "=f"(b) : "l"(v));
}
__device__ __forceinline__ void ffma2(unsigned long long& d, unsigned long long a, unsigned long long b) {
    asm("fma.rn.f32x2 %0, %1, %2, %0;" : "+l"(d) : "l"(a), "l"(b));
}
__device__ __forceinline__ uint32_t ex2h2(float a, float b) {
    __half2 h = __floats2half2_rn(a, b);
    uint32_t in = *(uint32_t*)&h, r;
    asm("ex2.approx.f16x2 %0, %1;" : "=r"(r) : "r"(in));
    return r;
}
__device__ __forceinline__ void cpasync16(uint32_t dst, const void* src) {
    asm volatile("cp.async.ca.shared.global [%0], [%1], 16;" :: "r"(dst), "l"(src));
}
#define CP_COMMIT() asm volatile("cp.async.commit_group;" ::: "memory")
#define CP_WAIT1()  asm volatile("cp.async.wait_group 1;" ::: "memory")

__device__ __forceinline__ void ldm4(uint32_t* r, uint32_t a) {
    asm volatile("ldmatrix.sync.aligned.m8n8.x4.shared.b16 {%0,%1,%2,%3}, [%4];"
                 : "=r"(r[0]), "=r"(r[1]), "=r"(r[2]), "=r"(r[3]) : "r"(a));
}
__device__ __forceinline__ void ldm4t(uint32_t* r, uint32_t a) {
    asm volatile("ldmatrix.sync.aligned.m8n8.x4.trans.shared.b16 {%0,%1,%2,%3}, [%4];"
                 : "=r"(r[0]), "=r"(r[1]), "=r"(r[2]), "=r"(r[3]) : "r"(a));
}
__device__ __forceinline__ void mma16(float* d, const uint32_t* a, const uint32_t* b) {
    asm volatile(
        "mma.sync.aligned.m16n8k16.row.col.f32.f16.f16.f32 "
        "{%0,%1,%2,%3}, {%4,%5,%6,%7}, {%8,%9}, {%0,%1,%2,%3};"
        : "+f"(d[0]), "+f"(d[1]), "+f"(d[2]), "+f"(d[3])
        : "r"(a[0]), "r"(a[1]), "r"(a[2]), "r"(a[3]), "r"(b[0]), "r"(b[1]));
}

// ===========================================================================
// Kernel 1: Wh = h@W (FFMA2), emit fp16 Wh[row][d] + fp32 e_src/e_dst
// 256 blocks x 256 threads (2 CTAs/SM -> 1 wave), 64 rows per block.
// ===========================================================================
__global__ __launch_bounds__(256, 2) void k_proj(const float* __restrict__ h,
                                                 const float* __restrict__ W,
                                                 const float* __restrict__ a_src,
                                                 const float* __restrict__ a_dst) {
    __shared__ float sbuf[128 * 66];  // [k][row], pitch 66

    const int t = threadIdx.x, tx = t & 31, ty = t >> 5;
    const int grow0 = blockIdx.x * 64;

    const float4* h4 = ((const float4*)h) + (size_t)grow0 * 32;
#pragma unroll
    for (int q = 0; q < 8; q++) {
        int idx = t + 256 * q;
        int row = idx >> 5, k4 = idx & 31;
        float4 v = h4[idx];
        sbuf[(k4 * 4 + 0) * 66 + row] = v.x;
        sbuf[(k4 * 4 + 1) * 66 + row] = v.y;
        sbuf[(k4 * 4 + 2) * 66 + row] = v.z;
        sbuf[(k4 * 4 + 3) * 66 + row] = v.w;
    }
    __syncthreads();

    unsigned long long ax[4] = {0, 0, 0, 0}, ay[4] = {0, 0, 0, 0},
                       az[4] = {0, 0, 0, 0}, aw[4] = {0, 0, 0, 0};
    const float4* W4 = (const float4*)W;
    for (int k = 0; k < 128; k++) {
        float4 w = __ldg(&W4[k * 32 + tx]);
        unsigned long long wxx = pk2(w.x, w.x), wyy = pk2(w.y, w.y);
        unsigned long long wzz = pk2(w.z, w.z), www = pk2(w.w, w.w);
        const float* hp = &sbuf[k * 66 + ty * 8];
#pragma unroll
        for (int pr = 0; pr < 4; pr++) {
            unsigned long long hh = *(const unsigned long long*)(hp + pr * 2);
            ffma2(ax[pr], hh, wxx);
            ffma2(ay[pr], hh, wyy);
            ffma2(az[pr], hh, wzz);
            ffma2(aw[pr], hh, www);
        }
    }

    float4 as = __ldg(((const float4*)a_src) + tx);
    float4 ad = __ldg(((const float4*)a_dst) + tx);
    uint2* Whh2 = (uint2*)g_Whh;
#pragma unroll
    for (int pr = 0; pr < 4; pr++) {
        float x0, x1, y0, y1, z0, z1, w0, w1;
        upk2(ax[pr], x0, x1); upk2(ay[pr], y0, y1);
        upk2(az[pr], z0, z1); upk2(aw[pr], w0, w1);
        int r0 = grow0 + ty * 8 + pr * 2;
        __half2 h01a = __floats2half2_rn(x0, y0), h23a = __floats2half2_rn(z0, w0);
        __half2 h01b = __floats2half2_rn(x1, y1), h23b = __floats2half2_rn(z1, w1);
        uint2 va, vb;
        va.x = *(uint32_t*)&h01a; va.y = *(uint32_t*)&h23a;
        vb.x = *(uint32_t*)&h01b; vb.y = *(uint32_t*)&h23b;
        Whh2[(size_t)r0 * 32 + tx] = va;
        Whh2[(size_t)(r0 + 1) * 32 + tx] = vb;
        float ps0 = x0 * as.x + y0 * as.y + z0 * as.z + w0 * as.w;
        float ps1 = x1 * as.x + y1 * as.y + z1 * as.z + w1 * as.w;
        float pd0 = x0 * ad.x + y0 * ad.y + z0 * ad.z + w0 * ad.w;
        float pd1 = x1 * ad.x + y1 * ad.y + z1 * ad.z + w1 * ad.w;
#pragma unroll
        for (int o = 16; o > 0; o >>= 1) {
            ps0 += __shfl_xor_sync(0xffffffffu, ps0, o);
            ps1 += __shfl_xor_sync(0xffffffffu, ps1, o);
            pd0 += __shfl_xor_sync(0xffffffffu, pd0, o);
            pd1 += __shfl_xor_sync(0xffffffffu, pd1, o);
        }
        if (tx == 0) {
            g_es[r0] = ps0; g_es[r0 + 1] = ps1;
            g_ed[r0] = pd0; g_ed[r0 + 1] = pd1;
        }
    }
}

// ===========================================================================
// Kernel 1b: pack adjacency bitmask (blocks 0..511) + e_dst max (blocks 512..519)
// ===========================================================================
__global__ __launch_bounds__(256) void k_mask(const int* __restrict__ adj) {
    if (blockIdx.x >= 512) {
        __shared__ float red[256];
        const int b = blockIdx.x - 512, t = threadIdx.x;
        float m = -1e30f;
#pragma unroll
        for (int q = 0; q < 8; q++) m = fmaxf(m, g_ed[b * NN + t + 256 * q]);
        red[t] = m;
        __syncthreads();
        for (int s = 128; s > 0; s >>= 1) {
            if (t < s) red[t] = fmaxf(red[t], red[t + s]);
            __syncthreads();
        }
        if (t == 0) g_edmax[b] = red[0];
        return;
    }
    const int g = blockIdx.x * 256 + threadIdx.x;
    const int i = g >> 6, w = g & 63;
    const int4* a4 = ((const int4*)adj) + (size_t)i * 512 + w * 8;
    unsigned bits = 0;
#pragma unroll
    for (int q = 0; q < 8; q++) {
        int4 v = __ldg(&a4[q]);
        bits |= (v.x > 0 ? 1u : 0u) << (q * 4 + 0);
        bits |= (v.y > 0 ? 1u : 0u) << (q * 4 + 1);
        bits |= (v.z > 0 ? 1u : 0u) << (q * 4 + 2);
        bits |= (v.w > 0 ? 1u : 0u) << (q * 4 + 3);
    }
    g_mask[g] = bits;
}

// ===========================================================================
// Kernel 2: fused masked attention + f16x2 exp + fp16 mma.sync P@Wh
// grid (32, 8): 64 i-rows per block, 256 threads (8 warps, 4M x 2N), 2 CTAs/SM.
// Row sums (softmax denominators) computed by MMA against an all-ones B tile.
// smem:
//   Whs[3][32 x 272B]  @ 0       (26112 B)  fp16 Wh tile, pitch 272
//   Ps [2][64 x 80B]   @ 26112   (10240 B)  fp16 probabilities, pitch 80
//   eds[2048]f         @ 36352   (8192 B)
// ===========================================================================
#define WHS_OFF  0u
#define WHS_BUF  8704u
#define WHS_PIT  272u
#define PS_OFF   26112u
#define PS_BUF   5120u
#define PS_PIT   80u
#define EDS_OFF  36352u
#define SMEM_SZ  44544u
#define ONES_H2  0x3C003C00u

__global__ __launch_bounds__(256, 2) void k_attn(float* __restrict__ out) {
    extern __shared__ __align__(16) char smem[];
    const uint32_t sbase = smem_u32(smem);

    const int t = threadIdx.x, wid = t >> 5, lane = t & 31;
    const int gid = lane >> 2, tid4 = lane & 3;
    const int wm = wid & 3, wn = wid >> 2;          // 4(M) x 2(N) warp grid
    const int b = blockIdx.y, i0 = blockIdx.x * 64;
    const int row = t >> 2, q4 = t & 3;             // producer mapping: 8 j/thread

    const __half* Whb = g_Whh + (size_t)b * NN * DD;

    // ldmatrix lane offsets (buffer-relative)
    const uint32_t offA = (uint32_t)((wm * 16 + (lane & 15)) * PS_PIT + (lane >> 4) * 16);
    const uint32_t offB = (uint32_t)((((lane >> 3) & 1) * 8 + (lane & 7)) * WHS_PIT +
                                     wn * 128 + (lane >> 4) * 16);

    // ---- prologue: cp Wh tile 0, tile 1; load eds ----
#pragma unroll
    for (int q = 0; q < 2; q++) {
        int idx = t + 256 * q;
        int rr = idx >> 4, cc = idx & 15;
        cpasync16(sbase + WHS_OFF + (uint32_t)(rr * WHS_PIT + cc * 16),
                  Whb + (size_t)rr * DD + cc * 8);
    }
    CP_COMMIT();
#pragma unroll
    for (int q = 0; q < 2; q++) {
        int idx = t + 256 * q;
        int rr = idx >> 4, cc = idx & 15;
        cpasync16(sbase + WHS_OFF + WHS_BUF + (uint32_t)(rr * WHS_PIT + cc * 16),
                  Whb + (size_t)(32 + rr) * DD + cc * 8);
    }
    CP_COMMIT();
    {
        float4* ed4 = (float4*)(smem + EDS_OFF);
        const float4* edsrc = ((const float4*)g_ed) + b * 512;
        ed4[t] = edsrc[t];
        ed4[t + 256] = edsrc[t + 256];
    }
    __syncthreads();  // eds visible

    const float esr = __ldg(g_es + b * NN + i0 + row);
    const float edm = __ldg(&g_edmax[b]);
    const float xm = esr + edm;
    const float m2r = fmaxf(xm, ALPHA_F * xm) * LOG2E_F;

    const uint8_t* mrow = ((const uint8_t*)g_mask) + (size_t)(i0 + row) * 256 + q4;

    float acc[8][4];
#pragma unroll
    for (int nt = 0; nt < 8; nt++)
#pragma unroll
        for (int c = 0; c < 4; c++) acc[nt][c] = 0.f;
    float accl[4] = {0.f, 0.f, 0.f, 0.f};
    const uint32_t bones[2] = {ONES_H2, ONES_H2};

    // ---- produce P(0) ----
    {
        unsigned mb = (unsigned)__ldg(mrow);
        const float* edt = (const float*)(smem + EDS_OFF) + q4 * 8;
        float4 e0 = *(const float4*)edt, e1 = *(const float4*)(edt + 4);
        float a0, a1, a2, a3, a4, a5, a6, a7;
        {
            float x, l;
            x = esr + e0.x; l = fmaxf(x, ALPHA_F * x); a0 = (mb & 1)   ? fmaf(l, LOG2E_F, -m2r) : -1e4f;
            x = esr + e0.y; l = fmaxf(x, ALPHA_F * x); a1 = (mb & 2)   ? fmaf(l, LOG2E_F, -m2r) : -1e4f;
            x = esr + e0.z; l = fmaxf(x, ALPHA_F * x); a2 = (mb & 4)   ? fmaf(l, LOG2E_F, -m2r) : -1e4f;
            x = esr + e0.w; l = fmaxf(x, ALPHA_F * x); a3 = (mb & 8)   ? fmaf(l, LOG2E_F, -m2r) : -1e4f;
            x = esr + e1.x; l = fmaxf(x, ALPHA_F * x); a4 = (mb & 16)  ? fmaf(l, LOG2E_F, -m2r) : -1e4f;
            x = esr + e1.y; l = fmaxf(x, ALPHA_F * x); a5 = (mb & 32)  ? fmaf(l, LOG2E_F, -m2r) : -1e4f;
            x = esr + e1.z; l = fmaxf(x, ALPHA_F * x); a6 = (mb & 64)  ? fmaf(l, LOG2E_F, -m2r) : -1e4f;
            x = esr + e1.w; l = fmaxf(x, ALPHA_F * x); a7 = (mb & 128) ? fmaf(l, LOG2E_F, -m2r) : -1e4f;
        }
        uint4 pv = make_uint4(ex2h2(a0, a1), ex2h2(a2, a3), ex2h2(a4, a5), ex2h2(a6, a7));
        *(uint4*)(smem + PS_OFF + (uint32_t)(row * PS_PIT + q4 * 16)) = pv;
    }
    CP_WAIT1();
    __syncthreads();  // P(0) + Wh(0) visible

    int wbuf = 2, rbuf = 0;
    for (int k = 0; k < 64; k++) {
        // ---- stage 1: cp.async Wh(k+2) ----
        if (k < 62) {
            const int j2 = (k + 2) * 32;
            uint32_t dstb = sbase + WHS_OFF + (uint32_t)wbuf * WHS_BUF;
#pragma unroll
            for (int q = 0; q < 2; q++) {
                int idx = t + 256 * q;
                int rr = idx >> 4, cc = idx & 15;
                cpasync16(dstb + (uint32_t)(rr * WHS_PIT + cc * 16),
                          Whb + (size_t)(j2 + rr) * DD + cc * 8);
            }
        }
        CP_COMMIT();

        // ---- stage 2: produce P(k+1) ----
        if (k < 63) {
            const int kt = k + 1;
            unsigned mb = (unsigned)__ldg(mrow + kt * 4);
            const float* edt = (const float*)(smem + EDS_OFF) + kt * 32 + q4 * 8;
            float4 e0 = *(const float4*)edt, e1 = *(const float4*)(edt + 4);
            float a0, a1, a2, a3, a4, a5, a6, a7;
            {
                float x, l;
                x = esr + e0.x; l = fmaxf(x, ALPHA_F * x); a0 = (mb & 1)   ? fmaf(l, LOG2E_F, -m2r) : -1e4f;
                x = esr + e0.y; l = fmaxf(x, ALPHA_F * x); a1 = (mb & 2)   ? fmaf(l, LOG2E_F, -m2r) : -1e4f;
                x = esr + e0.z; l = fmaxf(x, ALPHA_F * x); a2 = (mb & 4)   ? fmaf(l, LOG2E_F, -m2r) : -1e4f;
                x = esr + e0.w; l = fmaxf(x, ALPHA_F * x); a3 = (mb & 8)   ? fmaf(l, LOG2E_F, -m2r) : -1e4f;
                x = esr + e1.x; l = fmaxf(x, ALPHA_F * x); a4 = (mb & 16)  ? fmaf(l, LOG2E_F, -m2r) : -1e4f;
                x = esr + e1.y; l = fmaxf(x, ALPHA_F * x); a5 = (mb & 32)  ? fmaf(l, LOG2E_F, -m2r) : -1e4f;
                x = esr + e1.z; l = fmaxf(x, ALPHA_F * x); a6 = (mb & 64)  ? fmaf(l, LOG2E_F, -m2r) : -1e4f;
                x = esr + e1.w; l = fmaxf(x, ALPHA_F * x); a7 = (mb & 128) ? fmaf(l, LOG2E_F, -m2r) : -1e4f;
            }
            uint4 pv = make_uint4(ex2h2(a0, a1), ex2h2(a2, a3), ex2h2(a4, a5), ex2h2(a6, a7));
            *(uint4*)(smem + PS_OFF + (uint32_t)((kt & 1) * PS_BUF) +
                      (uint32_t)(row * PS_PIT + q4 * 16)) = pv;
        }

        // ---- stage 3: MMA(k) ----
        {
            const uint32_t psB = sbase + PS_OFF + (uint32_t)((k & 1) * PS_BUF);
            const uint32_t whB = sbase + WHS_OFF + (uint32_t)rbuf * WHS_BUF;
#pragma unroll
            for (int kb = 0; kb < 2; kb++) {
                uint32_t A[4], Bv[4][4];
                ldm4(A, psB + offA + kb * 32);
#pragma unroll
                for (int nb2 = 0; nb2 < 4; nb2++)
                    ldm4t(Bv[nb2], whB + offB + nb2 * 32 + kb * 16 * WHS_PIT);
#pragma unroll
                for (int nb2 = 0; nb2 < 4; nb2++) {
                    mma16(acc[nb2 * 2],     A, &Bv[nb2][0]);
                    mma16(acc[nb2 * 2 + 1], A, &Bv[nb2][2]);
                }
                mma16(accl, A, bones);  // row sums
            }
        }

        CP_WAIT1();
        __syncthreads();

        wbuf = wbuf == 2 ? 0 : wbuf + 1;
        rbuf = rbuf == 2 ? 0 : rbuf + 1;
    }

    // ---- epilogue: normalize by MMA-computed row sums, write ----
    const float ivA = 1.0f / accl[0];   // row wm*16 + gid
    const float ivB = 1.0f / accl[2];   // row wm*16 + gid + 8
    float2* out2 = (float2*)out;
    {
        int rA = wm * 16 + gid;
        int rB = rA + 8;
        size_t baseA = ((size_t)(b * NN + i0 + rA) * 128) >> 1;
        size_t baseB = ((size_t)(b * NN + i0 + rB) * 128) >> 1;
#pragma unroll
        for (int nt = 0; nt < 8; nt++) {
            int colh = (wn * 64 + nt * 8 + tid4 * 2) >> 1;
            out2[baseA + colh] = make_float2(acc[nt][0] * ivA, acc[nt][1] * ivA);
            out2[baseB + colh] = make_float2(acc[nt][2] * ivB, acc[nt][3] * ivB);
        }
    }
}

// ===========================================================================
extern "C" void kernel_launch(void* const* d_in, const int* in_sizes, int n_in,
                              void* d_out, int out_size) {
    const float* h     = (const float*)d_in[0];
    const int*   adj   = (const int*)d_in[1];
    const float* W     = (const float*)d_in[2];
    const float* a_src = (const float*)d_in[3];
    const float* a_dst = (const float*)d_in[4];
    float* out = (float*)d_out;

    cudaFuncSetAttribute(k_attn, cudaFuncAttributeMaxDynamicSharedMemorySize, SMEM_SZ);

    k_proj<<<256, 256>>>(h, W, a_src, a_dst);
    k_mask<<<520, 256>>>(adj);
    k_attn<<<dim3(32, 8), 256, SMEM_SZ>>>(out);
}